// round 1
// baseline (speedup 1.0000x reference)
#include <cuda_runtime.h>
#include <cuda_bf16.h>
#include <math.h>
#include <float.h>

// Problem constants
#define B_  16
#define S_  128
#define V_  40000
#define D_  768
#define H_  12
#define HD_ 64
#define F_  3072
#define L_  12
#define T_  (B_ * S_)   // 2048 tokens

// ---------------------------------------------------------------------------
// Scratch (no allocation allowed -> __device__ globals)
// ---------------------------------------------------------------------------
__device__ float g_h [T_ * D_];
__device__ float g_q [T_ * D_];
__device__ float g_k [T_ * D_];
__device__ float g_v [T_ * D_];
__device__ float g_a [T_ * D_];
__device__ float g_r [T_ * D_];
__device__ float g_h1[T_ * D_];
__device__ float g_t [T_ * F_];

// ---------------------------------------------------------------------------
// Helpers
// ---------------------------------------------------------------------------
__device__ __forceinline__ float gelu_exact(float x) {
    return 0.5f * x * (1.0f + erff(x * 0.70710678118654752440f));
}

__device__ __forceinline__ float warp_sum(float v) {
    #pragma unroll
    for (int o = 16; o > 0; o >>= 1) v += __shfl_xor_sync(0xFFFFFFFFu, v, o);
    return v;
}

// ---------------------------------------------------------------------------
// Embedding: h[t, :] = bpe[x[t], :] + pe[t % S, :]
// ---------------------------------------------------------------------------
__global__ void __launch_bounds__(256) embed_kernel(
    const int* __restrict__ x, const float* __restrict__ bpe,
    const float* __restrict__ pe, float* __restrict__ h)
{
    int t = blockIdx.x;
    int s = t & (S_ - 1);
    long tok = x[t];
    const float* bp = bpe + tok * (long)D_;
    const float* pp = pe + (long)s * D_;
    float* hp = h + (long)t * D_;
    #pragma unroll
    for (int i = 0; i < 3; i++) {
        int c = threadIdx.x + i * 256;
        hp[c] = bp[c] + pp[c];
    }
}

// ---------------------------------------------------------------------------
// Generic SGEMM: C = A[M,K] * B[K,N] (+bias) (+residual / gelu)
// Tile 128x64, BK=32, 256 threads, 8x4 per thread.
// Batched over blockIdx.z via strideB/strideBias/strideC (element offsets).
// EPI: 0 = acc+bias ; 1 = res + acc + bias ; 2 = res + gelu(acc + bias)
// ---------------------------------------------------------------------------
#define BM 128
#define BN 64
#define BK 32

template<int EPI>
__global__ void __launch_bounds__(256) sgemm_kernel(
    const float* __restrict__ A, const float* __restrict__ Bm,
    const float* __restrict__ bias, const float* __restrict__ Res,
    float* __restrict__ C,
    int K, int ldb, int ldc,
    long strideB, int strideBias, int strideC)
{
    const float* Bz    = Bm   + (long)blockIdx.z * strideB;
    const float* biasz = bias + (long)blockIdx.z * strideBias;
    float*       Cz    = C    + (long)blockIdx.z * strideC;
    const float* Rz    = (EPI != 0) ? (Res + (long)blockIdx.z * strideC) : nullptr;

    __shared__ float As[BK][BM + 4];
    __shared__ float Bs[BK][BN + 4];

    const int tid  = threadIdx.x;
    const int row0 = blockIdx.x * BM;
    const int col0 = blockIdx.y * BN;

    const int tm0 = (tid / 16) * 8;
    const int tn0 = (tid % 16) * 4;

    const int a_row = tid / 8;   // 0..31
    const int a_c4  = tid % 8;   // float4 within 32-wide K
    const int b_row = tid / 16;  // 0..15
    const int b_c4  = tid % 16;  // float4 within 64-wide N

    float acc[8][4] = {};

    for (int k0 = 0; k0 < K; k0 += BK) {
        #pragma unroll
        for (int i = 0; i < 4; i++) {
            int m = a_row + i * 32;
            float4 av = *(const float4*)(A + (long)(row0 + m) * K + k0 + a_c4 * 4);
            As[a_c4 * 4 + 0][m] = av.x;
            As[a_c4 * 4 + 1][m] = av.y;
            As[a_c4 * 4 + 2][m] = av.z;
            As[a_c4 * 4 + 3][m] = av.w;
        }
        #pragma unroll
        for (int i = 0; i < 2; i++) {
            int kk = b_row + i * 16;
            *(float4*)&Bs[kk][b_c4 * 4] =
                *(const float4*)(Bz + (long)(k0 + kk) * ldb + col0 + b_c4 * 4);
        }
        __syncthreads();
        #pragma unroll
        for (int kk = 0; kk < BK; kk++) {
            float a0[8], b0[4];
            *(float4*)&a0[0] = *(const float4*)&As[kk][tm0];
            *(float4*)&a0[4] = *(const float4*)&As[kk][tm0 + 4];
            *(float4*)&b0[0] = *(const float4*)&Bs[kk][tn0];
            #pragma unroll
            for (int i = 0; i < 8; i++)
                #pragma unroll
                for (int j = 0; j < 4; j++)
                    acc[i][j] = fmaf(a0[i], b0[j], acc[i][j]);
        }
        __syncthreads();
    }

    float bv[4];
    *(float4*)bv = *(const float4*)(biasz + col0 + tn0);
    #pragma unroll
    for (int i = 0; i < 8; i++) {
        long off = (long)(row0 + tm0 + i) * ldc + col0 + tn0;
        float4 o;
        float* op = &o.x;
        if (EPI == 0) {
            #pragma unroll
            for (int j = 0; j < 4; j++) op[j] = acc[i][j] + bv[j];
        } else {
            float4 r = *(const float4*)(Rz + off);
            const float* rp = &r.x;
            if (EPI == 1) {
                #pragma unroll
                for (int j = 0; j < 4; j++) op[j] = rp[j] + acc[i][j] + bv[j];
            } else {
                #pragma unroll
                for (int j = 0; j < 4; j++) op[j] = rp[j] + gelu_exact(acc[i][j] + bv[j]);
            }
        }
        *(float4*)(Cz + off) = o;
    }
}

// ---------------------------------------------------------------------------
// Attention: one block per (b,h), 128 threads (1 query row each).
// smem: KV tile [128][64] (K then reused for V), P [128][129].
// ---------------------------------------------------------------------------
#define ATTN_SMEM ((128 * 64 + 128 * 129) * 4)

__global__ void __launch_bounds__(128) attn_kernel(
    const float* __restrict__ q, const float* __restrict__ k,
    const float* __restrict__ v, const int* __restrict__ ignore,
    float* __restrict__ out)
{
    extern __shared__ float sm[];
    float* KV = sm;                // [128][64]
    float* P  = sm + 128 * 64;     // [128][129]
    __shared__ int ig[S_];

    const int bh = blockIdx.x;
    const int b  = bh / H_;
    const int h  = bh % H_;
    const int tid = threadIdx.x;
    const long base = (long)b * S_ * D_ + (long)h * HD_;

    ig[tid] = ignore[b * S_ + tid];

    // Stage K tile
    #pragma unroll
    for (int i = 0; i < 16; i++) {
        int idx = tid + i * 128;              // 0..2047 float4s
        int row = idx >> 4;
        int c4  = idx & 15;
        *(float4*)&KV[row * 64 + c4 * 4] =
            *(const float4*)(k + base + (long)row * D_ + c4 * 4);
    }
    // Own query row into registers
    float qr[64];
    #pragma unroll
    for (int i = 0; i < 16; i++)
        *(float4*)&qr[i * 4] = *(const float4*)(q + base + (long)tid * D_ + i * 4);
    __syncthreads();

    // Scores + mask + running max
    float mx = -FLT_MAX;
    for (int kk = 0; kk < S_; kk++) {
        float s = 0.f;
        #pragma unroll
        for (int e = 0; e < 64; e += 4) {
            float4 kv = *(const float4*)&KV[kk * 64 + e];
            s = fmaf(qr[e + 0], kv.x, s);
            s = fmaf(qr[e + 1], kv.y, s);
            s = fmaf(qr[e + 2], kv.z, s);
            s = fmaf(qr[e + 3], kv.w, s);
        }
        bool allowed = (kk <= tid) && (ig[kk] == 0 || kk == tid);
        float val = allowed ? s * 0.125f : -FLT_MAX;
        P[tid * 129 + kk] = val;
        mx = fmaxf(mx, val);
    }
    __syncthreads();   // all threads done reading K region

    // Stage V tile (overwrites KV) while doing softmax on own row
    #pragma unroll
    for (int i = 0; i < 16; i++) {
        int idx = tid + i * 128;
        int row = idx >> 4;
        int c4  = idx & 15;
        *(float4*)&KV[row * 64 + c4 * 4] =
            *(const float4*)(v + base + (long)row * D_ + c4 * 4);
    }
    float sum = 0.f;
    for (int kk = 0; kk < S_; kk++) {
        float e = expf(P[tid * 129 + kk] - mx);
        P[tid * 129 + kk] = e;
        sum += e;
    }
    float inv = 1.0f / sum;
    __syncthreads();

    // O = P @ V
    float acc[64] = {};
    for (int kk = 0; kk < S_; kk++) {
        float p = P[tid * 129 + kk];
        #pragma unroll
        for (int e = 0; e < 64; e += 4) {
            float4 vv = *(const float4*)&KV[kk * 64 + e];
            acc[e + 0] = fmaf(p, vv.x, acc[e + 0]);
            acc[e + 1] = fmaf(p, vv.y, acc[e + 1]);
            acc[e + 2] = fmaf(p, vv.z, acc[e + 2]);
            acc[e + 3] = fmaf(p, vv.w, acc[e + 3]);
        }
    }
    #pragma unroll
    for (int i = 0; i < 16; i++) {
        float4 o = make_float4(acc[i * 4] * inv, acc[i * 4 + 1] * inv,
                               acc[i * 4 + 2] * inv, acc[i * 4 + 3] * inv);
        *(float4*)(out + base + (long)tid * D_ + i * 4) = o;
    }
}

// ---------------------------------------------------------------------------
// LayerNorm: out = (x - mu) * rsqrt(var + eps) * w + b  (one block per row)
// ---------------------------------------------------------------------------
__global__ void __launch_bounds__(256) ln_kernel(
    const float* __restrict__ x, const float* __restrict__ w,
    const float* __restrict__ b, float* __restrict__ out)
{
    const int row = blockIdx.x;
    const int tid = threadIdx.x;
    const float* xr = x + (long)row * D_;

    float v[3], s = 0.f, s2 = 0.f;
    #pragma unroll
    for (int i = 0; i < 3; i++) {
        v[i] = xr[tid + i * 256];
        s += v[i];
        s2 = fmaf(v[i], v[i], s2);
    }
    s  = warp_sum(s);
    s2 = warp_sum(s2);
    __shared__ float sh[16];
    int wid = tid >> 5, lane = tid & 31;
    if (lane == 0) { sh[wid] = s; sh[8 + wid] = s2; }
    __syncthreads();
    if (tid == 0) {
        float a = 0.f, a2 = 0.f;
        #pragma unroll
        for (int i = 0; i < 8; i++) { a += sh[i]; a2 += sh[8 + i]; }
        sh[0] = a; sh[1] = a2;
    }
    __syncthreads();
    float mu  = sh[0] * (1.0f / D_);
    float var = sh[1] * (1.0f / D_) - mu * mu;
    float rs  = rsqrtf(var + 1e-5f);
    float* op = out + (long)row * D_;
    #pragma unroll
    for (int i = 0; i < 3; i++) {
        int c = tid + i * 256;
        op[c] = (v[i] - mu) * rs * w[c] + b[c];
    }
}

// ---------------------------------------------------------------------------
// Launch
// ---------------------------------------------------------------------------
extern "C" void kernel_launch(void* const* d_in, const int* in_sizes, int n_in,
                              void* d_out, int out_size)
{
    const int*   x      = (const int*)  d_in[0];
    const int*   ignore = (const int*)  d_in[1];
    const float* bpe    = (const float*)d_in[2];
    const float* pe     = (const float*)d_in[3];
    const float* Wq     = (const float*)d_in[4];
    const float* bq     = (const float*)d_in[5];
    const float* Wk     = (const float*)d_in[6];
    const float* bk     = (const float*)d_in[7];
    const float* Wv     = (const float*)d_in[8];
    const float* bv     = (const float*)d_in[9];
    const float* Wo     = (const float*)d_in[10];
    const float* bo     = (const float*)d_in[11];
    const float* W1     = (const float*)d_in[12];
    const float* b1     = (const float*)d_in[13];
    const float* W2     = (const float*)d_in[14];
    const float* b2     = (const float*)d_in[15];
    const float* ln1w   = (const float*)d_in[16];
    const float* ln1b   = (const float*)d_in[17];
    const float* ln2w   = (const float*)d_in[18];
    const float* ln2b   = (const float*)d_in[19];
    const float* Wout   = (const float*)d_in[20];
    const float* bout   = (const float*)d_in[21];
    float* out = (float*)d_out;

    cudaFuncSetAttribute(attn_kernel,
        cudaFuncAttributeMaxDynamicSharedMemorySize, ATTN_SMEM);

    float *h, *q, *k, *v, *a, *r, *h1, *t;
    cudaGetSymbolAddress((void**)&h,  g_h);
    cudaGetSymbolAddress((void**)&q,  g_q);
    cudaGetSymbolAddress((void**)&k,  g_k);
    cudaGetSymbolAddress((void**)&v,  g_v);
    cudaGetSymbolAddress((void**)&a,  g_a);
    cudaGetSymbolAddress((void**)&r,  g_r);
    cudaGetSymbolAddress((void**)&h1, g_h1);
    cudaGetSymbolAddress((void**)&t,  g_t);

    embed_kernel<<<T_, 256>>>(x, bpe, pe, h);

    for (int l = 0; l < L_; l++) {
        const float* Wq_l = Wq + (long)l * H_ * D_ * HD_;
        const float* Wk_l = Wk + (long)l * H_ * D_ * HD_;
        const float* Wv_l = Wv + (long)l * H_ * D_ * HD_;
        const float* bq_l = bq + (long)l * H_ * HD_;
        const float* bk_l = bk + (long)l * H_ * HD_;
        const float* bv_l = bv + (long)l * H_ * HD_;
        const float* Wo_l = Wo + (long)l * D_ * D_;
        const float* bo_l = bo + (long)l * D_;
        const float* W1_l = W1 + (long)l * D_ * F_;
        const float* b1_l = b1 + (long)l * F_;
        const float* W2_l = W2 + (long)l * F_ * D_;
        const float* b2_l = b2 + (long)l * D_;

        // QKV: batched per head, B[h] = [D, HD] row-major, C cols h*64..
        dim3 gqkv(T_ / BM, 1, H_);
        sgemm_kernel<0><<<gqkv, 256>>>(h, Wq_l, bq_l, nullptr, q,
                                       D_, HD_, D_, (long)D_ * HD_, HD_, HD_);
        sgemm_kernel<0><<<gqkv, 256>>>(h, Wk_l, bk_l, nullptr, k,
                                       D_, HD_, D_, (long)D_ * HD_, HD_, HD_);
        sgemm_kernel<0><<<gqkv, 256>>>(h, Wv_l, bv_l, nullptr, v,
                                       D_, HD_, D_, (long)D_ * HD_, HD_, HD_);

        attn_kernel<<<B_ * H_, 128, ATTN_SMEM>>>(q, k, v, ignore, a);

        // r = h + a @ Wo + bo
        sgemm_kernel<1><<<dim3(T_ / BM, D_ / BN, 1), 256>>>(
            a, Wo_l, bo_l, h, r, D_, D_, D_, 0, 0, 0);
        // h1 = LN1(r)
        ln_kernel<<<T_, 256>>>(r, ln1w + (long)l * D_, ln1b + (long)l * D_, h1);
        // t = h1 @ W1 + b1
        sgemm_kernel<0><<<dim3(T_ / BM, F_ / BN, 1), 256>>>(
            h1, W1_l, b1_l, nullptr, t, D_, F_, F_, 0, 0, 0);
        // r = h1 + gelu(t @ W2 + b2)
        sgemm_kernel<2><<<dim3(T_ / BM, D_ / BN, 1), 256>>>(
            t, W2_l, b2_l, h1, r, F_, D_, D_, 0, 0, 0);
        // h = LN2(r)
        ln_kernel<<<T_, 256>>>(r, ln2w + (long)l * D_, ln2b + (long)l * D_, h);
    }

    // logits = h @ Wout + bout
    sgemm_kernel<0><<<dim3(T_ / BM, V_ / BN, 1), 256>>>(
        h, Wout, bout, nullptr, out, D_, V_, V_, 0, 0, 0);
}